// round 15
// baseline (speedup 1.0000x reference)
#include <cuda_runtime.h>
#include <cstdint>

// Problem constants (shapes fixed by the dataset)
#define BB   64
#define KK   8
#define VV   128000
#define NS   25              // chunks per batch row
#define TPB  256
#define NW   (TPB / 32)      // 8 warps per block
#define LCH  (VV / NS)       // 5120 floats per chunk
#define SEG  128             // floats per segment (one warp-wide float4 iter)
#define SPW  5               // segments per warp (5*128 = 640 floats)
#define WPB_BATCH (NS * NW)  // 200 warps per batch
#define SEGS_B (WPB_BATCH * SPW)   // 1000 segments per batch
#define FULL 0xFFFFFFFFu

// Scratch (device globals — zero-initialized; g_done self-resets every call)
__device__ float g_ssum[BB * SEGS_B];      // per-segment sums (b*1000 + wf*5 + i)
__device__ float g_wsum[BB * WPB_BATCH];   // per-warp sums    (b*200 + wf)
__device__ int   g_done[BB];

// ---------------------------------------------------------------------------
// Hierarchical CDF search for one batch (run by the last-retiring warp).
// level 1: 200 warp sums -> level 2: 5 segment sums -> level 3: 128 floats.
// All scan orders match construction orders exactly (level 3 via fallback).
// ---------------------------------------------------------------------------
__device__ __forceinline__ void cdf_search(int b, int na, int allacc, int r,
                                           const float* __restrict__ dp,
                                           const float* __restrict__ op,
                                           const float* __restrict__ su,
                                           float* __restrict__ out, int lane)
{
    // ---- level 1: 200 warp sums, prefetched (7 groups of 32) ----
    float w[7];
#pragma unroll
    for (int g = 0; g < 7; ++g) {
        int j = g * 32 + lane;
        w[g] = (j < WPB_BATCH) ? __ldcg(&g_wsum[b * WPB_BATCH + j]) : 0.0f;
    }
    // total in the same carry order as the crossing scan below
    float xtop[7];
    float tot = 0.0f;
#pragma unroll
    for (int g = 0; g < 7; ++g) {
        float xx = w[g];
#pragma unroll
        for (int o = 1; o < 32; o <<= 1) {
            float y = __shfl_up_sync(FULL, xx, o);
            if (lane >= o) xx += y;
        }
        xtop[g] = __shfl_sync(FULL, xx, 31);
        tot += xtop[g];
    }
    float T = allacc ? su[b] : su[b] * tot;

    int   wf = -1;
    float basew = 0.0f, running = 0.0f;
#pragma unroll
    for (int g = 0; g < 7; ++g) {
        float xx = w[g];
#pragma unroll
        for (int o = 1; o < 32; o <<= 1) {
            float y = __shfl_up_sync(FULL, xx, o);
            if (lane >= o) xx += y;
        }
        int j = g * 32 + lane;
        unsigned bal = __ballot_sync(FULL, (j < WPB_BATCH) && (running + xx >= T));
        if (bal) {
            int l = __ffs(bal) - 1;
            wf    = g * 32 + l;
            basew = running + __shfl_sync(FULL, xx, l) - __shfl_sync(FULL, w[g], l);
            break;
        }
        running += xtop[g];
    }

    int token;
    if (wf < 0) {
        token = VV - 1;                                  // u beyond total mass
    } else {
        // ---- level 2: 5 segment sums of warp wf ----
        float sv = (lane < SPW) ? __ldcg(&g_ssum[b * SEGS_B + wf * SPW + lane]) : 0.0f;
        float xx = sv;
#pragma unroll
        for (int o = 1; o < 32; o <<= 1) {
            float y = __shfl_up_sync(FULL, xx, o);
            if (lane >= o) xx += y;
        }
        unsigned b2 = __ballot_sync(FULL, (lane < SPW) && (basew + xx >= T));
        if (!b2) {
            token = min((wf + 1) * (SPW * SEG), VV - 1); // ulp-tie fallback
        } else {
            int i = __ffs(b2) - 1;
            float base_t = basew + __shfl_sync(FULL, xx, i)
                                 - __shfl_sync(FULL, sv, i);

            // ---- level 3: one 128-float segment, coalesced re-read ----
            int off0 = (wf * SPW + i) * SEG;
            int ob2  = (b * (KK + 1) + (allacc ? KK : r)) * VV + off0;
            int db2  = (b * KK + r) * VV + off0;
            float4 ov = ((const float4*)(op + ob2))[lane];
            float v0, v1, v2, v3;
            if (allacc) {
                v0 = ov.x; v1 = ov.y; v2 = ov.z; v3 = ov.w;
            } else {
                float4 dv = ((const float4*)(dp + db2))[lane];
                v0 = fmaxf(ov.x - dv.x, 0.f); v1 = fmaxf(ov.y - dv.y, 0.f);
                v2 = fmaxf(ov.z - dv.z, 0.f); v3 = fmaxf(ov.w - dv.w, 0.f);
            }
            float local = v0 + v1 + v2 + v3;
            float xs = local;
#pragma unroll
            for (int o = 1; o < 32; o <<= 1) {
                float y = __shfl_up_sync(FULL, xs, o);
                if (lane >= o) xs += y;
            }
            unsigned b3 = __ballot_sync(FULL, base_t + xs >= T);
            if (!b3) {
                token = min(off0 + SEG, VV - 1);          // ulp-tie fallback
            } else {
                int l = __ffs(b3) - 1;
                float excl = base_t + __shfl_sync(FULL, xs, l)
                                    - __shfl_sync(FULL, local, l);
                float a0 = __shfl_sync(FULL, v0, l);
                float a1 = __shfl_sync(FULL, v1, l);
                float a2 = __shfl_sync(FULL, v2, l);
                float run = excl;
                int idx = 3;
                run += a0;
                if (run >= T) idx = 0;
                else { run += a1;
                    if (run >= T) idx = 1;
                    else { run += a2; if (run >= T) idx = 2; }
                }
                token = min(off0 + l * 4 + idx, VV - 1);
            }
        }
    }

    if (lane == 0)
        out[b * (KK + 1) + na] = (float)token;
}

// ---------------------------------------------------------------------------
// Fused kernel — R7 streaming core with fully independent warp retirement:
// no shared memory, no __syncthreads. Each warp stores its 5 segment sums +
// its warp total, fences, bumps the per-batch warp counter, and exits; the
// 200th warp runs the CDF search.
// ---------------------------------------------------------------------------
__global__ void __launch_bounds__(TPB, 4)
k_fused(const int*   __restrict__ dtok,
        const float* __restrict__ dp,
        const float* __restrict__ op,
        const float* __restrict__ unif,
        const float* __restrict__ su,
        float*       __restrict__ out)
{
    int blk = blockIdx.x;
    int b = blk / NS, s = blk % NS;
    int t = threadIdx.x, lane = t & 31, wid = t >> 5;
    int wf = s * NW + wid;                   // warp index within batch (0..199)

    // ---- acceptance, computed redundantly per warp (L2-hot) ----
    bool acc = false;
    if (lane < KK) {
        int tok  = dtok[b * KK + lane];
        float pd = dp[(b * KK + lane) * VV + tok];
        float po = op[(b * (KK + 1) + lane) * VV + tok];
        acc = unif[b * KK + lane] < fminf(1.0f, po / pd);
    }
    unsigned bits = __ballot_sync(FULL, acc) & ((1u << KK) - 1u);
    int na     = __ffs(~bits) - 1;           // 8 if all accepted
    int allacc = (na == KK);
    int r      = min(na, KK - 1);

    // ---- coalesced streaming: 5 oracle (+5 draft) float4 loads up front ----
    int row  = s * LCH;
    int base = wid * (SPW * 32);
    const float4* o4 = (const float4*)(op + (b * (KK + 1) + (allacc ? KK : r)) * VV + row);
    const float4* d4 = (const float4*)(dp + (b * KK + r) * VV + row);

    float4 a0 = o4[base + 0 * 32 + lane];
    float4 a1 = o4[base + 1 * 32 + lane];
    float4 a2 = o4[base + 2 * 32 + lane];
    float4 a3 = o4[base + 3 * 32 + lane];
    float4 a4 = o4[base + 4 * 32 + lane];

    float p[SPW];
    if (allacc) {
        p[0] = a0.x + a0.y + a0.z + a0.w;
        p[1] = a1.x + a1.y + a1.z + a1.w;
        p[2] = a2.x + a2.y + a2.z + a2.w;
        p[3] = a3.x + a3.y + a3.z + a3.w;
        p[4] = a4.x + a4.y + a4.z + a4.w;
    } else {
        float4 e0 = d4[base + 0 * 32 + lane];
        float4 e1 = d4[base + 1 * 32 + lane];
        float4 e2 = d4[base + 2 * 32 + lane];
        float4 e3 = d4[base + 3 * 32 + lane];
        float4 e4 = d4[base + 4 * 32 + lane];
        p[0] = fmaxf(a0.x - e0.x, 0.f) + fmaxf(a0.y - e0.y, 0.f)
             + fmaxf(a0.z - e0.z, 0.f) + fmaxf(a0.w - e0.w, 0.f);
        p[1] = fmaxf(a1.x - e1.x, 0.f) + fmaxf(a1.y - e1.y, 0.f)
             + fmaxf(a1.z - e1.z, 0.f) + fmaxf(a1.w - e1.w, 0.f);
        p[2] = fmaxf(a2.x - e2.x, 0.f) + fmaxf(a2.y - e2.y, 0.f)
             + fmaxf(a2.z - e2.z, 0.f) + fmaxf(a2.w - e2.w, 0.f);
        p[3] = fmaxf(a3.x - e3.x, 0.f) + fmaxf(a3.y - e3.y, 0.f)
             + fmaxf(a3.z - e3.z, 0.f) + fmaxf(a3.w - e3.w, 0.f);
        p[4] = fmaxf(a4.x - e4.x, 0.f) + fmaxf(a4.y - e4.y, 0.f)
             + fmaxf(a4.z - e4.z, 0.f) + fmaxf(a4.w - e4.w, 0.f);
    }

    // ---- segment sums (5 independent warp tree-reduces) ----
#pragma unroll
    for (int i = 0; i < SPW; ++i) {
        float ww = p[i];
#pragma unroll
        for (int o = 16; o > 0; o >>= 1)
            ww += __shfl_down_sync(FULL, ww, o);
        p[i] = ww;                           // lane 0 holds the segment sum
    }

    // ---- token scaffolding (chunk s==0, warp 0's threads; no sync needed) ----
    if (s == 0) {
        if (t <= KK && t != na)
            out[b * (KK + 1) + t] = (t < na) ? (float)dtok[b * KK + t] : -1.0f;
        if (t == KK + 1)
            out[BB * (KK + 1) + b] = (float)na;
    }

    // ---- publish (lane 0) + per-warp done counting; warps retire freely ----
    int last = 0;
    if (lane == 0) {
        float wsum = ((((p[0] + p[1]) + p[2]) + p[3]) + p[4]);  // scan order
#pragma unroll
        for (int i = 0; i < SPW; ++i)
            g_ssum[b * SEGS_B + wf * SPW + i] = p[i];
        g_wsum[b * WPB_BATCH + wf] = wsum;
        __threadfence();                     // make this warp's sums visible
        int old = atomicAdd(&g_done[b], 1);
        last = (old == WPB_BATCH - 1);
        if (last) g_done[b] = 0;             // self-reset for graph replay
    }
    last = __shfl_sync(FULL, last, 0);
    if (!last) return;

    __threadfence();                         // acquire before cross-block reads
    cdf_search(b, na, allacc, r, dp, op, su, out, lane);
}

// ---------------------------------------------------------------------------
// Host launcher: classify inputs by element count (order-agnostic).
// ---------------------------------------------------------------------------
extern "C" void kernel_launch(void* const* d_in, const int* in_sizes, int n_in,
                              void* d_out, int out_size)
{
    const int*   dtok = nullptr;
    const float* dp   = nullptr;
    const float* op   = nullptr;
    const float* unif = nullptr;
    const float* su   = nullptr;

    int n512 = 0;
    for (int i = 0; i < n_in; ++i) {
        long sz = (long)in_sizes[i];
        if (sz == (long)BB * KK * VV)            dp = (const float*)d_in[i];
        else if (sz == (long)BB * (KK + 1) * VV) op = (const float*)d_in[i];
        else if (sz == BB)                       su = (const float*)d_in[i];
        else if (sz == BB * KK) {
            // relative order: draft_tokens, oracle_tokens, uniforms
            if      (n512 == 0) dtok = (const int*)d_in[i];
            else if (n512 == 2) unif = (const float*)d_in[i];
            ++n512;
        }
    }

    float* out = (float*)d_out;  // [tokens (B*(K+1)) | num_accepted (B)] as f32

    k_fused<<<BB * NS, TPB>>>(dtok, dp, op, unif, su, out);
}

// round 16
// speedup vs baseline: 1.1214x; 1.1214x over previous
#include <cuda_runtime.h>
#include <cstdint>

// Problem constants (shapes fixed by the dataset)
#define BB   64
#define KK   8
#define VV   128000
#define NS   25              // chunks per batch row
#define TPB  256
#define NW   (TPB / 32)      // 8 warps per block
#define LCH  (VV / NS)       // 5120 floats per chunk
#define SEG  128             // floats per segment (one warp-wide float4 iter)
#define SPW  5               // segments per warp (5*128 = 640 floats)
#define SEGS (NW * SPW)      // 40 segments per chunk
#define FULL 0xFFFFFFFFu

// Scratch (device globals — zero-initialized; g_done self-resets every call)
__device__ float g_ssum[BB * NS * SEGS];     // per-segment sums (256 KB)
__device__ float g_chunksum[BB * NS];
__device__ int   g_done[BB];

// ---------------------------------------------------------------------------
// Hierarchical CDF search for one batch (warp 0 of the last-done block).
// level 1: 25 chunk sums -> level 2: 40 segment sums -> level 3: 128 floats.
// Scan orders match construction orders exactly (group-scan with carry).
// ---------------------------------------------------------------------------
__device__ __forceinline__ void cdf_search(int b, int na, int allacc, int r,
                                           const float* __restrict__ dp,
                                           const float* __restrict__ op,
                                           const float* __restrict__ su,
                                           float* __restrict__ out, int lane)
{
    // level 1: 25 chunk sums
    float cs = (lane < NS) ? __ldcg(&g_chunksum[b * NS + lane]) : 0.0f;
    float x = cs;
#pragma unroll
    for (int o = 1; o < 32; o <<= 1) {
        float y = __shfl_up_sync(FULL, x, o);
        if (lane >= o) x += y;
    }
    float tot = __shfl_sync(FULL, x, NS - 1);
    float T = allacc ? su[b] : su[b] * tot;

    unsigned bal = __ballot_sync(FULL, (lane < NS) && (x >= T));
    int token;
    if (bal == 0) {
        token = VV - 1;                              // u beyond total mass
    } else {
        int sc = __ffs(bal) - 1;                     // chunk with the crossing
        float base = __shfl_sync(FULL, x, sc) - __shfl_sync(FULL, cs, sc);

        // level 2: 40 segment sums, two group-scans with carry
        const float* ss = &g_ssum[(b * NS + sc) * SEGS];
        int   j_found = -1;
        float base_t  = 0.0f;
        float running = base;
#pragma unroll
        for (int g = 0; g < 2; ++g) {
            int j = g * 32 + lane;
            float v = (j < SEGS) ? __ldcg(&ss[j]) : 0.0f;
            float xx = v;
#pragma unroll
            for (int o = 1; o < 32; o <<= 1) {
                float y = __shfl_up_sync(FULL, xx, o);
                if (lane >= o) xx += y;
            }
            unsigned bb2 = __ballot_sync(FULL, (j < SEGS) && (running + xx >= T));
            if (bb2) {
                int l = __ffs(bb2) - 1;
                j_found = g * 32 + l;
                base_t  = running + __shfl_sync(FULL, xx, l)
                                  - __shfl_sync(FULL, v, l);
                break;
            }
            running += __shfl_sync(FULL, xx, 31);
        }

        if (j_found < 0) {
            token = min(sc * LCH + LCH, VV - 1);     // ulp-tie fallback
        } else {
            // level 3: one 128-float segment, coalesced re-read
            int off0 = sc * LCH + j_found * SEG;
            int ob2  = (b * (KK + 1) + (allacc ? KK : r)) * VV + off0;
            int db2  = (b * KK + r) * VV + off0;
            float4 ov = ((const float4*)(op + ob2))[lane];
            float v0, v1, v2, v3;
            if (allacc) {
                v0 = ov.x; v1 = ov.y; v2 = ov.z; v3 = ov.w;
            } else {
                float4 dv = ((const float4*)(dp + db2))[lane];
                v0 = fmaxf(ov.x - dv.x, 0.f); v1 = fmaxf(ov.y - dv.y, 0.f);
                v2 = fmaxf(ov.z - dv.z, 0.f); v3 = fmaxf(ov.w - dv.w, 0.f);
            }
            float local = v0 + v1 + v2 + v3;
            float xs = local;
#pragma unroll
            for (int o = 1; o < 32; o <<= 1) {
                float y = __shfl_up_sync(FULL, xs, o);
                if (lane >= o) xs += y;
            }
            unsigned bb3 = __ballot_sync(FULL, base_t + xs >= T);
            if (!bb3) {
                token = min(off0 + SEG, VV - 1);      // ulp-tie fallback
            } else {
                int l = __ffs(bb3) - 1;
                float excl = base_t + __shfl_sync(FULL, xs, l)
                                    - __shfl_sync(FULL, local, l);
                float a0 = __shfl_sync(FULL, v0, l);
                float a1 = __shfl_sync(FULL, v1, l);
                float a2 = __shfl_sync(FULL, v2, l);
                float run = excl;
                int idx = 3;
                run += a0;
                if (run >= T) idx = 0;
                else { run += a1;
                    if (run >= T) idx = 1;
                    else { run += a2; if (run >= T) idx = 2; }
                }
                token = min(off0 + l * 4 + idx, VV - 1);
            }
        }
    }

    if (lane == 0)
        out[b * (KK + 1) + na] = (float)token;
}

// ---------------------------------------------------------------------------
// Fused kernel — R7's proven structure (NS=25, TPB=256, per-warp acceptance,
// 5+5 front-batched float4 streaming, shared segment sums, ONE atomic per
// block), with the only change being a slimmer epilogue: a single
// __syncthreads, after which warps 1-7 retire immediately and warp 0 handles
// chunk sum + publish + (if last) the CDF search.
// ---------------------------------------------------------------------------
__global__ void __launch_bounds__(TPB, 4)
k_fused(const int*   __restrict__ dtok,
        const float* __restrict__ dp,
        const float* __restrict__ op,
        const float* __restrict__ unif,
        const float* __restrict__ su,
        float*       __restrict__ out)
{
    __shared__ float ssh[SEGS];

    int blk = blockIdx.x;
    int b = blk / NS, s = blk % NS;
    int t = threadIdx.x, lane = t & 31, wid = t >> 5;

    // ---- acceptance, computed redundantly per warp (L2-hot) ----
    bool acc = false;
    if (lane < KK) {
        int tok  = dtok[b * KK + lane];
        float pd = dp[(b * KK + lane) * VV + tok];
        float po = op[(b * (KK + 1) + lane) * VV + tok];
        acc = unif[b * KK + lane] < fminf(1.0f, po / pd);
    }
    unsigned bits = __ballot_sync(FULL, acc) & ((1u << KK) - 1u);
    int na     = __ffs(~bits) - 1;          // 8 if all accepted
    int allacc = (na == KK);
    int r      = min(na, KK - 1);

    // ---- coalesced streaming: 5 oracle (+5 draft) float4 loads up front ----
    int row  = s * LCH;
    int base = wid * (SPW * 32);
    const float4* o4 = (const float4*)(op + (b * (KK + 1) + (allacc ? KK : r)) * VV + row);
    const float4* d4 = (const float4*)(dp + (b * KK + r) * VV + row);

    float4 a0 = o4[base + 0 * 32 + lane];
    float4 a1 = o4[base + 1 * 32 + lane];
    float4 a2 = o4[base + 2 * 32 + lane];
    float4 a3 = o4[base + 3 * 32 + lane];
    float4 a4 = o4[base + 4 * 32 + lane];

    float p[SPW];
    if (allacc) {
        p[0] = a0.x + a0.y + a0.z + a0.w;
        p[1] = a1.x + a1.y + a1.z + a1.w;
        p[2] = a2.x + a2.y + a2.z + a2.w;
        p[3] = a3.x + a3.y + a3.z + a3.w;
        p[4] = a4.x + a4.y + a4.z + a4.w;
    } else {
        float4 e0 = d4[base + 0 * 32 + lane];
        float4 e1 = d4[base + 1 * 32 + lane];
        float4 e2 = d4[base + 2 * 32 + lane];
        float4 e3 = d4[base + 3 * 32 + lane];
        float4 e4 = d4[base + 4 * 32 + lane];
        p[0] = fmaxf(a0.x - e0.x, 0.f) + fmaxf(a0.y - e0.y, 0.f)
             + fmaxf(a0.z - e0.z, 0.f) + fmaxf(a0.w - e0.w, 0.f);
        p[1] = fmaxf(a1.x - e1.x, 0.f) + fmaxf(a1.y - e1.y, 0.f)
             + fmaxf(a1.z - e1.z, 0.f) + fmaxf(a1.w - e1.w, 0.f);
        p[2] = fmaxf(a2.x - e2.x, 0.f) + fmaxf(a2.y - e2.y, 0.f)
             + fmaxf(a2.z - e2.z, 0.f) + fmaxf(a2.w - e2.w, 0.f);
        p[3] = fmaxf(a3.x - e3.x, 0.f) + fmaxf(a3.y - e3.y, 0.f)
             + fmaxf(a3.z - e3.z, 0.f) + fmaxf(a3.w - e3.w, 0.f);
        p[4] = fmaxf(a4.x - e4.x, 0.f) + fmaxf(a4.y - e4.y, 0.f)
             + fmaxf(a4.z - e4.z, 0.f) + fmaxf(a4.w - e4.w, 0.f);
    }

    // ---- segment sums (5 independent warp tree-reduces) ----
#pragma unroll
    for (int i = 0; i < SPW; ++i) {
        float w = p[i];
#pragma unroll
        for (int o = 16; o > 0; o >>= 1)
            w += __shfl_down_sync(FULL, w, o);
        if (lane == 0) {
            ssh[wid * SPW + i] = w;
            g_ssum[blk * SEGS + wid * SPW + i] = w;
        }
    }

    // ---- token scaffolding (chunk s==0 writes all slots except na) ----
    if (s == 0) {
        if (t <= KK && t != na)
            out[b * (KK + 1) + t] = (t < na) ? (float)dtok[b * KK + t] : -1.0f;
        if (t == KK + 1)
            out[BB * (KK + 1) + b] = (float)na;
    }

    __syncthreads();                 // ssh / g_ssum stores done
    if (wid != 0) return;            // warps 1-7 retire immediately

    // ---- chunk sum: 2 group-scans with carry (same order as level 2) ----
    float run = 0.0f;
#pragma unroll
    for (int g = 0; g < 2; ++g) {
        int j = g * 32 + lane;
        float v = (j < SEGS) ? ssh[j] : 0.0f;
        float xx = v;
#pragma unroll
        for (int o = 1; o < 32; o <<= 1) {
            float y = __shfl_up_sync(FULL, xx, o);
            if (lane >= o) xx += y;
        }
        run += __shfl_sync(FULL, xx, 31);
    }

    // ---- publish + elect last block of this batch (one atomic per block) ----
    int last = 0;
    if (lane == 0) {
        g_chunksum[blk] = run;
        __threadfence();             // make this block's sums device-visible
        int old = atomicAdd(&g_done[b], 1);
        last = (old == NS - 1);
        if (last) g_done[b] = 0;     // self-reset for graph replay
    }
    last = __shfl_sync(FULL, last, 0);
    if (!last) return;

    __threadfence();                 // acquire before cross-block reads
    cdf_search(b, na, allacc, r, dp, op, su, out, lane);
}

// ---------------------------------------------------------------------------
// Host launcher: classify inputs by element count (order-agnostic).
// ---------------------------------------------------------------------------
extern "C" void kernel_launch(void* const* d_in, const int* in_sizes, int n_in,
                              void* d_out, int out_size)
{
    const int*   dtok = nullptr;
    const float* dp   = nullptr;
    const float* op   = nullptr;
    const float* unif = nullptr;
    const float* su   = nullptr;

    int n512 = 0;
    for (int i = 0; i < n_in; ++i) {
        long sz = (long)in_sizes[i];
        if (sz == (long)BB * KK * VV)            dp = (const float*)d_in[i];
        else if (sz == (long)BB * (KK + 1) * VV) op = (const float*)d_in[i];
        else if (sz == BB)                       su = (const float*)d_in[i];
        else if (sz == BB * KK) {
            // relative order: draft_tokens, oracle_tokens, uniforms
            if      (n512 == 0) dtok = (const int*)d_in[i];
            else if (n512 == 2) unif = (const float*)d_in[i];
            ++n512;
        }
    }

    float* out = (float*)d_out;  // [tokens (B*(K+1)) | num_accepted (B)] as f32

    k_fused<<<BB * NS, TPB>>>(dtok, dp, op, unif, su, out);
}

// round 17
// speedup vs baseline: 1.1236x; 1.0019x over previous
#include <cuda_runtime.h>
#include <cstdint>

// Problem constants (shapes fixed by the dataset)
#define BB   64
#define KK   8
#define VV   128000
#define NS   25              // chunks per batch row
#define TPB  256
#define NW   (TPB / 32)      // 8 warps per block
#define LCH  (VV / NS)       // 5120 floats per chunk
#define SEG  128             // floats per segment (one warp-wide float4 iter)
#define SPW  5               // segments per warp (5*128 = 640 floats)
#define SEGS (NW * SPW)      // 40 segments per chunk
#define FULL 0xFFFFFFFFu

// Scratch (device globals — zero-initialized; g_done self-resets every call)
__device__ float g_ssum[BB * NS * SEGS];     // per-segment sums (256 KB)
__device__ float g_chunksum[BB * NS];
__device__ int   g_done[BB];

// ---------------------------------------------------------------------------
// Single fused kernel, fully-coalesced streaming (round-7 configuration —
// the empirical optimum of every axis probed in rounds 8-16):
//   * per-WARP acceptance (no block barrier on the load-issue critical path)
//   * warp-wide float4 iterations: each LDG.128 covers 512 contiguous bytes
//   * search hierarchy: 25 chunk sums -> 40 segment sums -> 128-float segment
// ---------------------------------------------------------------------------
__global__ void __launch_bounds__(TPB, 4)
k_fused(const int*   __restrict__ dtok,
        const float* __restrict__ dp,
        const float* __restrict__ op,
        const float* __restrict__ unif,
        const float* __restrict__ su,
        float*       __restrict__ out)
{
    int blk = blockIdx.x;
    int b = blk / NS, s = blk % NS;
    int t = threadIdx.x, lane = t & 31, wid = t >> 5;

    // ---- acceptance, computed redundantly per warp (L2/L1-hot) ----
    bool acc = false;
    if (lane < KK) {
        int tok  = dtok[b * KK + lane];
        float pd = dp[((long)b * KK + lane) * VV + tok];
        float po = op[((long)b * (KK + 1) + lane) * VV + tok];
        acc = unif[b * KK + lane] < fminf(1.0f, po / pd);
    }
    unsigned bits = __ballot_sync(FULL, acc) & ((1u << KK) - 1u);
    int na     = __ffs(~bits) - 1;          // 8 if all accepted
    int allacc = (na == KK) ? 1 : 0;
    int r      = min(na, KK - 1);

    // ---- coalesced streaming: warp covers 640 contiguous floats ----
    long row_off = (long)s * LCH + wid * (SPW * SEG);
    long obase   = ((long)b * (KK + 1) + (allacc ? KK : r)) * VV + row_off;
    long dbase   = ((long)b * KK + r) * VV + row_off;
    const float4* o4 = (const float4*)(op + obase);
    const float4* d4 = (const float4*)(dp + dbase);

    float p0, p1, p2, p3, p4;               // per-lane sums, one per segment
    if (allacc) {
        float4 a0 = o4[lane],      a1 = o4[32 + lane], a2 = o4[64 + lane];
        float4 a3 = o4[96 + lane], a4 = o4[128 + lane];
        p0 = a0.x + a0.y + a0.z + a0.w;
        p1 = a1.x + a1.y + a1.z + a1.w;
        p2 = a2.x + a2.y + a2.z + a2.w;
        p3 = a3.x + a3.y + a3.z + a3.w;
        p4 = a4.x + a4.y + a4.z + a4.w;
    } else {
        float4 a0 = o4[lane],      a1 = o4[32 + lane], a2 = o4[64 + lane];
        float4 a3 = o4[96 + lane], a4 = o4[128 + lane];
        float4 e0 = d4[lane],      e1 = d4[32 + lane], e2 = d4[64 + lane];
        float4 e3 = d4[96 + lane], e4 = d4[128 + lane];
        p0 = fmaxf(a0.x - e0.x, 0.f) + fmaxf(a0.y - e0.y, 0.f)
           + fmaxf(a0.z - e0.z, 0.f) + fmaxf(a0.w - e0.w, 0.f);
        p1 = fmaxf(a1.x - e1.x, 0.f) + fmaxf(a1.y - e1.y, 0.f)
           + fmaxf(a1.z - e1.z, 0.f) + fmaxf(a1.w - e1.w, 0.f);
        p2 = fmaxf(a2.x - e2.x, 0.f) + fmaxf(a2.y - e2.y, 0.f)
           + fmaxf(a2.z - e2.z, 0.f) + fmaxf(a2.w - e2.w, 0.f);
        p3 = fmaxf(a3.x - e3.x, 0.f) + fmaxf(a3.y - e3.y, 0.f)
           + fmaxf(a3.z - e3.z, 0.f) + fmaxf(a3.w - e3.w, 0.f);
        p4 = fmaxf(a4.x - e4.x, 0.f) + fmaxf(a4.y - e4.y, 0.f)
           + fmaxf(a4.z - e4.z, 0.f) + fmaxf(a4.w - e4.w, 0.f);
    }

    // ---- segment sums: warp tree-reduce each iteration ----
    __shared__ float ssh[SEGS];
    float q[SPW] = {p0, p1, p2, p3, p4};
#pragma unroll
    for (int i = 0; i < SPW; ++i) {
        float w = q[i];
#pragma unroll
        for (int o = 16; o > 0; o >>= 1)
            w += __shfl_down_sync(FULL, w, o);
        if (lane == 0) {
            ssh[wid * SPW + i] = w;
            g_ssum[(long)blk * SEGS + wid * SPW + i] = w;
        }
    }

    // ---- token scaffolding (block s==0 writes all slots except na) ----
    if (s == 0) {
        if (t <= KK && t != na)
            out[b * (KK + 1) + t] = (t < na) ? (float)dtok[b * KK + t] : -1.0f;
        if (t == 0)
            out[BB * (KK + 1) + b] = (float)na;
    }

    __syncthreads();
    if (t == 0) {
        float c = 0.0f;                      // sequential over segments:
#pragma unroll                               // consistent with level-2 search
        for (int j = 0; j < SEGS; ++j) c += ssh[j];
        g_chunksum[blk] = c;
    }

    // ---- publish + elect last block of this batch ----
    __shared__ int sh_last;
    __syncthreads();
    if (t == 0) {
        __threadfence();
        int old = atomicAdd(&g_done[b], 1);
        sh_last = (old == NS - 1);
    }
    __syncthreads();
    if (!sh_last) return;
    if (t == 0) g_done[b] = 0;               // self-reset for graph replay
    if (wid != 0) return;

    __threadfence();                          // acquire before cross-block reads

    // ---- level 1: 25 chunk sums ----
    float cs = (lane < NS) ? __ldcg(&g_chunksum[b * NS + lane]) : 0.0f;
    float x = cs;
#pragma unroll
    for (int o = 1; o < 32; o <<= 1) {
        float y = __shfl_up_sync(FULL, x, o);
        if (lane >= o) x += y;
    }
    float tot = __shfl_sync(FULL, x, NS - 1);
    float T = allacc ? su[b] : su[b] * tot;

    unsigned bal = __ballot_sync(FULL, (lane < NS) && (x >= T));
    int token;
    if (bal == 0) {
        token = VV - 1;
    } else {
        int sc = __ffs(bal) - 1;
        float base = __shfl_sync(FULL, x, sc) - __shfl_sync(FULL, cs, sc);

        // ---- level 2: 40 segment sums in chunk sc ----
        const float* ss = &g_ssum[(long)(b * NS + sc) * SEGS];
        int   j_found = -1;
        float base_t  = 0.0f;
        float running = base;
#pragma unroll
        for (int g = 0; g < 2; ++g) {
            int j = g * 32 + lane;
            float v = (j < SEGS) ? __ldcg(&ss[j]) : 0.0f;
            float xx = v;
#pragma unroll
            for (int o = 1; o < 32; o <<= 1) {
                float y = __shfl_up_sync(FULL, xx, o);
                if (lane >= o) xx += y;
            }
            unsigned bb2 = __ballot_sync(FULL, (j < SEGS) && (running + xx >= T));
            if (bb2) {
                int l = __ffs(bb2) - 1;
                j_found = g * 32 + l;
                base_t  = running + __shfl_sync(FULL, xx, l)
                                  - __shfl_sync(FULL, v, l);
                break;
            }
            running += __shfl_sync(FULL, xx, 31);
        }

        if (j_found < 0) {
            token = min(sc * LCH + LCH, VV - 1);     // ulp-tie fallback
        } else {
            // ---- level 3: one 128-float segment, coalesced re-read ----
            long off0 = (long)sc * LCH + (long)j_found * SEG;
            long ob2  = ((long)b * (KK + 1) + (allacc ? KK : r)) * VV + off0;
            long db2  = ((long)b * KK + r) * VV + off0;
            float4 ov = ((const float4*)(op + ob2))[lane];
            float v0, v1, v2, v3;
            if (allacc) {
                v0 = ov.x; v1 = ov.y; v2 = ov.z; v3 = ov.w;
            } else {
                float4 dv = ((const float4*)(dp + db2))[lane];
                v0 = fmaxf(ov.x - dv.x, 0.f); v1 = fmaxf(ov.y - dv.y, 0.f);
                v2 = fmaxf(ov.z - dv.z, 0.f); v3 = fmaxf(ov.w - dv.w, 0.f);
            }
            float local = v0 + v1 + v2 + v3;
            float xx = local;
#pragma unroll
            for (int o = 1; o < 32; o <<= 1) {
                float y = __shfl_up_sync(FULL, xx, o);
                if (lane >= o) xx += y;
            }
            unsigned bb3 = __ballot_sync(FULL, base_t + xx >= T);
            if (!bb3) {
                token = min((int)(off0 + SEG), VV - 1);   // ulp-tie fallback
            } else {
                int l = __ffs(bb3) - 1;
                float excl = base_t + __shfl_sync(FULL, xx, l)
                                    - __shfl_sync(FULL, local, l);
                float a0 = __shfl_sync(FULL, v0, l);
                float a1 = __shfl_sync(FULL, v1, l);
                float a2 = __shfl_sync(FULL, v2, l);
                float a3 = __shfl_sync(FULL, v3, l);
                (void)a3;
                float run = excl;
                int idx = 3;
                run += a0;
                if (run >= T) idx = 0;
                else { run += a1;
                    if (run >= T) idx = 1;
                    else { run += a2; if (run >= T) idx = 2; }
                }
                token = min((int)(off0 + l * 4 + idx), VV - 1);
            }
        }
    }

    if (lane == 0)
        out[b * (KK + 1) + na] = (float)token;
}

// ---------------------------------------------------------------------------
// Host launcher: classify inputs by element count (order-agnostic).
// ---------------------------------------------------------------------------
extern "C" void kernel_launch(void* const* d_in, const int* in_sizes, int n_in,
                              void* d_out, int out_size)
{
    const int*   dtok = nullptr;
    const float* dp   = nullptr;
    const float* op   = nullptr;
    const float* unif = nullptr;
    const float* su   = nullptr;

    int n512 = 0;
    for (int i = 0; i < n_in; ++i) {
        long sz = (long)in_sizes[i];
        if (sz == (long)BB * KK * VV)            dp = (const float*)d_in[i];
        else if (sz == (long)BB * (KK + 1) * VV) op = (const float*)d_in[i];
        else if (sz == BB)                       su = (const float*)d_in[i];
        else if (sz == BB * KK) {
            // relative order: draft_tokens, oracle_tokens, uniforms
            if      (n512 == 0) dtok = (const int*)d_in[i];
            else if (n512 == 2) unif = (const float*)d_in[i];
            ++n512;
        }
    }

    float* out = (float*)d_out;  // [tokens (B*(K+1)) | num_accepted (B)] as f32

    k_fused<<<BB * NS, TPB>>>(dtok, dp, op, unif, su, out);
}